// round 8
// baseline (speedup 1.0000x reference)
#include <cuda_runtime.h>
#include <cuda_bf16.h>
#include <math.h>
#include <stdint.h>

#define FULL 0xffffffffu
typedef unsigned long long u64;

constexpr int Nn = 100000;
constexpr int Ee = 1600000;
constexpr int Gg = 1000;
constexpr int Ss = 32;
constexpr int Hh = 128;
constexpr int ROUNDS = 5;
constexpr float NEG_SLOPE = 0.01f;
constexpr float LN_EPS = 1e-5f;

constexpr int APITCH = 272;
constexpr int AWARP = 16 * APITCH;
constexpr int EDGE_WARPS = 6;                       // 192-thread blocks
constexpr int OFF_B_H = EDGE_WARPS * 2 * AWARP;     // 52224
constexpr int OFF_B_L = OFF_B_H + 32 * APITCH;      // 60928
constexpr int EDGE_DSMEM = OFF_B_L + 32 * APITCH;   // 69632  (3 blocks/SM)
constexpr int EDGE_GRID = 444;                      // 3 blocks/SM x 148 SMs

__device__ float g_state[2][Nn * Ss];
__device__ float g_y[Nn * Hh];
__device__ float4 g_stats[Nn];
__device__ float g_gs[Gg * Ss];

__device__ __forceinline__ float lrelu(float v) { return v >= 0.f ? v : NEG_SLOPE * v; }

// ---- packed f32x2 helpers ----
__device__ __forceinline__ u64 pack2(float lo, float hi) {
    u64 r; asm("mov.b64 %0,{%1,%2};" : "=l"(r) : "f"(lo), "f"(hi)); return r;
}
__device__ __forceinline__ void unpack2(u64 v, float& lo, float& hi) {
    asm("mov.b64 {%0,%1},%2;" : "=f"(lo), "=f"(hi) : "l"(v));
}
__device__ __forceinline__ u64 fma2(u64 a, u64 b, u64 c) {
    u64 d; asm("fma.rn.f32x2 %0,%1,%2,%3;" : "=l"(d) : "l"(a), "l"(b), "l"(c)); return d;
}
__device__ __forceinline__ u64 add2(u64 a, u64 b) {
    u64 d; asm("add.rn.f32x2 %0,%1,%2;" : "=l"(d) : "l"(a), "l"(b)); return d;
}
__device__ __forceinline__ u64 mul2(u64 a, u64 b) {
    u64 d; asm("mul.rn.f32x2 %0,%1,%2;" : "=l"(d) : "l"(a), "l"(b)); return d;
}

__device__ __forceinline__ uint32_t smem_u32(const void* p) {
    uint32_t a;
    asm("{ .reg .u64 t; cvta.to.shared.u64 t, %1; cvt.u32.u64 %0, t; }" : "=r"(a) : "l"(p));
    return a;
}

__device__ __forceinline__ void ldsm4(uint32_t r[4], uint32_t addr) {
    asm volatile("ldmatrix.sync.aligned.m8n8.x4.shared.b16 {%0,%1,%2,%3}, [%4];"
                 : "=r"(r[0]), "=r"(r[1]), "=r"(r[2]), "=r"(r[3]) : "r"(addr));
}

__device__ __forceinline__ void mma16816(float acc[4], const uint32_t a[4],
                                         uint32_t b0, uint32_t b1) {
    asm volatile(
        "mma.sync.aligned.m16n8k16.row.col.f32.bf16.bf16.f32 "
        "{%0,%1,%2,%3}, {%4,%5,%6,%7}, {%8,%9}, {%0,%1,%2,%3};"
        : "+f"(acc[0]), "+f"(acc[1]), "+f"(acc[2]), "+f"(acc[3])
        : "r"(a[0]), "r"(a[1]), "r"(a[2]), "r"(a[3]), "r"(b0), "r"(b1));
}

// ---------------------------------------------------------------------------
__global__ void zero_kernel() {
    int i = blockIdx.x * blockDim.x + threadIdx.x;
    int stride = gridDim.x * blockDim.x;
    for (int k = i; k < Nn * Ss; k += stride) g_state[0][k] = 0.f;
    for (int k = i; k < Gg * Ss; k += stride) g_gs[k] = 0.f;
}

// ---------------------------------------------------------------------------
// y = state @ W1[:32] + b1 ; stats (Sy,Qy,P) ; fused copy.  4 nodes/warp
// (reverted from 8-node blocking: regs 91->63, occupancy back up)
__global__ void __launch_bounds__(192) node_gemm_kernel(
    int inb, const float* __restrict__ W1, const float* __restrict__ b1)
{
    __shared__ float sW1[32 * 128];
    __shared__ float sb1[128];
    const float* __restrict__ state_in = g_state[inb];
    float* __restrict__ state_out = g_state[inb ^ 1];

    int tid = threadIdx.x;
    for (int i = tid; i < 32 * 128; i += 192) sW1[i] = W1[i];
    if (tid < 128) sb1[tid] = b1[tid];
    __syncthreads();

    int lane = tid & 31;
    int w = tid >> 5;
    int warp_global = blockIdx.x * 6 + w;
    int nwarps = gridDim.x * 6;
    int ngroups = Nn / 4;

    float4 b1v = *(const float4*)&sb1[4 * lane];
    float4 w32v = *(const float4*)&W1[32 * 128 + 4 * lane];

    for (int g = warp_global; g < ngroups; g += nwarps) {
        int nbase = g * 4;
        float x0 = state_in[(nbase + 0) * Ss + lane];
        float x1 = state_in[(nbase + 1) * Ss + lane];
        float x2 = state_in[(nbase + 2) * Ss + lane];
        float x3 = state_in[(nbase + 3) * Ss + lane];

        state_out[(nbase + 0) * Ss + lane] = x0;   // fused copy
        state_out[(nbase + 1) * Ss + lane] = x1;
        state_out[(nbase + 2) * Ss + lane] = x2;
        state_out[(nbase + 3) * Ss + lane] = x3;

        float4 a0 = b1v, a1 = b1v, a2 = b1v, a3 = b1v;
#pragma unroll
        for (int i = 0; i < 32; i++) {
            float4 wv = *(const float4*)&sW1[i * 128 + 4 * lane];
            float s0 = __shfl_sync(FULL, x0, i);
            float s1 = __shfl_sync(FULL, x1, i);
            float s2 = __shfl_sync(FULL, x2, i);
            float s3 = __shfl_sync(FULL, x3, i);
            a0.x += s0 * wv.x; a0.y += s0 * wv.y; a0.z += s0 * wv.z; a0.w += s0 * wv.w;
            a1.x += s1 * wv.x; a1.y += s1 * wv.y; a1.z += s1 * wv.z; a1.w += s1 * wv.w;
            a2.x += s2 * wv.x; a2.y += s2 * wv.y; a2.z += s2 * wv.z; a2.w += s2 * wv.w;
            a3.x += s3 * wv.x; a3.y += s3 * wv.y; a3.z += s3 * wv.z; a3.w += s3 * wv.w;
        }
        *(float4*)&g_y[(nbase + 0) * Hh + 4 * lane] = a0;
        *(float4*)&g_y[(nbase + 1) * Hh + 4 * lane] = a1;
        *(float4*)&g_y[(nbase + 2) * Hh + 4 * lane] = a2;
        *(float4*)&g_y[(nbase + 3) * Hh + 4 * lane] = a3;

#pragma unroll
        for (int e = 0; e < 4; e++) {
            float4 a = (e == 0) ? a0 : (e == 1) ? a1 : (e == 2) ? a2 : a3;
            float s = a.x + a.y + a.z + a.w;
            float q = a.x * a.x + a.y * a.y + a.z * a.z + a.w * a.w;
            float p = a.x * w32v.x + a.y * w32v.y + a.z * w32v.z + a.w * w32v.w;
#pragma unroll
            for (int o = 16; o; o >>= 1) {
                s += __shfl_xor_sync(FULL, s, o);
                q += __shfl_xor_sync(FULL, q, o);
                p += __shfl_xor_sync(FULL, p, o);
            }
            if (lane == 0) g_stats[nbase + e] = make_float4(s, q, p, 0.f);
        }
    }
}

// ---------------------------------------------------------------------------
// Edge kernel: 192 threads (6 warps), 3 blocks/SM -> 18 warps/SM.
__global__ void __launch_bounds__(192, 3) edge_kernel(
    int inb,
    const int* __restrict__ nf, const int* __restrict__ nt,
    const float* __restrict__ ec,
    const float* __restrict__ W1,
    const float* __restrict__ g1, const float* __restrict__ be1,
    const float* __restrict__ W2, const float* __restrict__ b2,
    const float* __restrict__ g2, const float* __restrict__ be2)
{
    extern __shared__ char dsm[];
    uint32_t sbase = smem_u32(dsm);

    int tid = threadIdx.x;
    int lane = tid & 31;
    int wid = tid >> 5;

    // B staging with column permutation pi(8t+2q+r) = 8q+2t+r
    for (int p = tid; p < 32 * 128; p += 192) {
        int n = p >> 7;
        int k = p & 127;
        int t = n >> 3, q0 = (n >> 1) & 3, r = n & 1;
        int pn = 8 * q0 + 2 * t + r;
        float wv = W2[k * 32 + pn];
        __nv_bfloat16 hb = __float2bfloat16(wv);
        __nv_bfloat16 lb = __float2bfloat16(wv - __bfloat162float(hb));
        *(__nv_bfloat16*)(dsm + OFF_B_H + n * APITCH + k * 2) = hb;
        *(__nv_bfloat16*)(dsm + OFF_B_L + n * APITCH + k * 2) = lb;
    }
    __syncthreads();

    float4 w32v = *(const float4*)&W1[32 * 128 + 4 * lane];
    float4 g1v  = *(const float4*)&g1[4 * lane];
    float4 be1v = *(const float4*)&be1[4 * lane];

    float Sw = w32v.x + w32v.y + w32v.z + w32v.w;
    float Qw = w32v.x * w32v.x + w32v.y * w32v.y + w32v.z * w32v.z + w32v.w * w32v.w;
#pragma unroll
    for (int o = 16; o; o >>= 1) {
        Sw += __shfl_xor_sync(FULL, Sw, o);
        Qw += __shfl_xor_sync(FULL, Qw, o);
    }

    int q = lane & 3;
    int rA = lane >> 2;
    int rB = rA + 8;

    u64 b2p[4], g2p[4], be2p[4];
#pragma unroll
    for (int t = 0; t < 4; t++) {
        int c = 8 * q + 2 * t;
        b2p[t]  = pack2(b2[c],  b2[c + 1]);
        g2p[t]  = pack2(g2[c],  g2[c + 1]);
        be2p[t] = pack2(be2[c], be2[c + 1]);
    }
    const u64 C001 = pack2(NEG_SLOPE, NEG_SLOPE);

    char* aStoreH = dsm + wid * 2 * AWARP + lane * 8;
    char* aStoreL = aStoreH + AWARP;

    int aRow = lane & 15;
    int aColB = ((lane >> 4) & 1) * 16;
    uint32_t ldAH = sbase + wid * 2 * AWARP + aRow * APITCH + aColB;
    uint32_t ldAL = ldAH + AWARP;

    int bRow = ((lane >> 4) & 1) * 8 + (lane & 7);
    int bKB = ((lane >> 3) & 1) * 16;
    uint32_t ldBH01 = sbase + OFF_B_H + bRow * APITCH + bKB;
    uint32_t ldBH23 = ldBH01 + 16 * APITCH;
    uint32_t ldBL01 = sbase + OFF_B_L + bRow * APITCH + bKB;
    uint32_t ldBL23 = ldBL01 + 16 * APITCH;

    const float4* __restrict__ yv = (const float4*)g_y;
    float* __restrict__ state_out = g_state[inb ^ 1];

    int ngroups = Ee / 16;
    int wg = blockIdx.x * EDGE_WARPS + wid;
    int nw = gridDim.x * EDGE_WARPS;

    for (int g = wg; g < ngroups; g += nw) {
        int base = g * 16;

        // ---- gather + stats-based LN1 + bf16 split + stage ----
#pragma unroll
        for (int j = 0; j < 4; j++) {
            int4 NF = *(const int4*)&nf[base + 4 * j];
            float4 C = *(const float4*)&ec[base + 4 * j];
            int srcs[4] = {NF.x, NF.y, NF.z, NF.w};
            float cs[4] = {C.x, C.y, C.z, C.w};
#pragma unroll
            for (int e = 0; e < 4; e++) {
                int src = srcs[e];
                float c = cs[e];
                float4 st = g_stats[src];
                float4 a = yv[src * (Hh / 4) + lane];
                a.x = fmaf(c, w32v.x, a.x);
                a.y = fmaf(c, w32v.y, a.y);
                a.z = fmaf(c, w32v.z, a.z);
                a.w = fmaf(c, w32v.w, a.w);

                float s = fmaf(c, Sw, st.x);
                float qq = fmaf(c * c, Qw, fmaf(2.f * c, st.z, st.y));
                float mean = s * (1.f / 128.f);
                float var = qq * (1.f / 128.f) - mean * mean;
                float rstd = rsqrtf(var + LN_EPS);

                float4 hv;
                hv.x = lrelu(fmaf((a.x - mean) * rstd, g1v.x, be1v.x));
                hv.y = lrelu(fmaf((a.y - mean) * rstd, g1v.y, be1v.y));
                hv.z = lrelu(fmaf((a.z - mean) * rstd, g1v.z, be1v.z));
                hv.w = lrelu(fmaf((a.w - mean) * rstd, g1v.w, be1v.w));

                __nv_bfloat162 h01 = __float22bfloat162_rn(make_float2(hv.x, hv.y));
                __nv_bfloat162 h23 = __float22bfloat162_rn(make_float2(hv.z, hv.w));
                float2 f01 = __bfloat1622float2(h01);
                float2 f23 = __bfloat1622float2(h23);
                __nv_bfloat162 l01 = __float22bfloat162_rn(make_float2(hv.x - f01.x, hv.y - f01.y));
                __nv_bfloat162 l23 = __float22bfloat162_rn(make_float2(hv.z - f23.x, hv.w - f23.y));
                u64 packh = (u64)(*(uint32_t*)&h01) | ((u64)(*(uint32_t*)&h23) << 32);
                u64 packl = (u64)(*(uint32_t*)&l01) | ((u64)(*(uint32_t*)&l23) << 32);
                int row = 4 * j + e;
                *(u64*)(aStoreH + row * APITCH) = packh;
                *(u64*)(aStoreL + row * APITCH) = packl;
            }
        }
        __syncwarp();

        // ---- MMA: D = Ah@Bh + Ah@Bl + Al@Bh ----
        float acc[4][4];
#pragma unroll
        for (int t = 0; t < 4; t++)
#pragma unroll
            for (int j2 = 0; j2 < 4; j2++) acc[t][j2] = 0.f;

#pragma unroll
        for (int k = 0; k < 8; k++) {
            uint32_t ah[4], al[4], bh01[4], bh23[4], bl01[4], bl23[4];
            ldsm4(ah, ldAH + k * 32);
            ldsm4(al, ldAL + k * 32);
            ldsm4(bh01, ldBH01 + k * 32);
            ldsm4(bh23, ldBH23 + k * 32);
            ldsm4(bl01, ldBL01 + k * 32);
            ldsm4(bl23, ldBL23 + k * 32);

            mma16816(acc[0], ah, bh01[0], bh01[1]);
            mma16816(acc[1], ah, bh01[2], bh01[3]);
            mma16816(acc[2], ah, bh23[0], bh23[1]);
            mma16816(acc[3], ah, bh23[2], bh23[3]);

            mma16816(acc[0], ah, bl01[0], bl01[1]);
            mma16816(acc[1], ah, bl01[2], bl01[3]);
            mma16816(acc[2], ah, bl23[0], bl23[1]);
            mma16816(acc[3], ah, bl23[2], bl23[3]);

            mma16816(acc[0], al, bh01[0], bh01[1]);
            mma16816(acc[1], al, bh01[2], bh01[3]);
            mma16816(acc[2], al, bh23[0], bh23[1]);
            mma16816(acc[3], al, bh23[2], bh23[3]);
        }
        __syncwarp();

        // ---- epilogue: packed bias + LN2 (quad reduction) + float4 scatter ----
        int dstA = __ldg(&nt[base + rA]);
        int dstB = __ldg(&nt[base + rB]);

        u64 mA[4], mB[4];
#pragma unroll
        for (int t = 0; t < 4; t++) {
            mA[t] = add2(pack2(acc[t][0], acc[t][1]), b2p[t]);
            mB[t] = add2(pack2(acc[t][2], acc[t][3]), b2p[t]);
        }
        u64 sA2 = add2(add2(mA[0], mA[1]), add2(mA[2], mA[3]));
        u64 sB2 = add2(add2(mB[0], mB[1]), add2(mB[2], mB[3]));
        u64 qA2 = fma2(mA[0], mA[0], fma2(mA[1], mA[1], fma2(mA[2], mA[2], mul2(mA[3], mA[3]))));
        u64 qB2 = fma2(mB[0], mB[0], fma2(mB[1], mB[1], fma2(mB[2], mB[2], mul2(mB[3], mB[3]))));
        float t0, t1;
        unpack2(sA2, t0, t1); float sA = t0 + t1;
        unpack2(qA2, t0, t1); float qA = t0 + t1;
        unpack2(sB2, t0, t1); float sB = t0 + t1;
        unpack2(qB2, t0, t1); float qB = t0 + t1;
#pragma unroll
        for (int o = 2; o; o >>= 1) {
            sA += __shfl_xor_sync(FULL, sA, o);
            qA += __shfl_xor_sync(FULL, qA, o);
            sB += __shfl_xor_sync(FULL, sB, o);
            qB += __shfl_xor_sync(FULL, qB, o);
        }
        float meanA = sA * (1.f / 32.f);
        float rstdA = rsqrtf(qA * (1.f / 32.f) - meanA * meanA + LN_EPS);
        float meanB = sB * (1.f / 32.f);
        float rstdB = rsqrtf(qB * (1.f / 32.f) - meanB * meanB + LN_EPS);

        u64 rA2p = pack2(rstdA, rstdA), nmA2 = pack2(-meanA, -meanA);
        u64 rB2p = pack2(rstdB, rstdB), nmB2 = pack2(-meanB, -meanB);

        float vA[8], vB[8];
#pragma unroll
        for (int t = 0; t < 4; t++) {
            u64 agA = mul2(rA2p, g2p[t]);
            u64 offA = fma2(nmA2, agA, be2p[t]);
            u64 hA = fma2(mA[t], agA, offA);
            u64 pA = mul2(hA, C001);
            float h0, h1, p0, p1;
            unpack2(hA, h0, h1); unpack2(pA, p0, p1);
            vA[2 * t] = fmaxf(h0, p0); vA[2 * t + 1] = fmaxf(h1, p1);

            u64 agB = mul2(rB2p, g2p[t]);
            u64 offB = fma2(nmB2, agB, be2p[t]);
            u64 hB = fma2(mB[t], agB, offB);
            u64 pB = mul2(hB, C001);
            unpack2(hB, h0, h1); unpack2(pB, p0, p1);
            vB[2 * t] = fmaxf(h0, p0); vB[2 * t + 1] = fmaxf(h1, p1);
        }

        float* rowA = &state_out[dstA * Ss + 8 * q];
        float* rowB = &state_out[dstB * Ss + 8 * q];
        atomicAdd((float4*)&rowA[0], make_float4(vA[0], vA[1], vA[2], vA[3]));
        atomicAdd((float4*)&rowA[4], make_float4(vA[4], vA[5], vA[6], vA[7]));
        atomicAdd((float4*)&rowB[0], make_float4(vB[0], vB[1], vB[2], vB[3]));
        atomicAdd((float4*)&rowB[4], make_float4(vB[4], vB[5], vB[6], vB[7]));
    }
}

// ---------------------------------------------------------------------------
__global__ void graphsum_kernel(int inb, const int* __restrict__ ngi) {
    int t = blockIdx.x * blockDim.x + threadIdx.x;
    int total = Nn * (Ss / 4);
    if (t >= total) return;
    int n = t >> 3;
    int q = t & 7;
    const float4* s = reinterpret_cast<const float4*>(g_state[inb]);
    float4 v = s[t];
    int g = ngi[n];
    atomicAdd(reinterpret_cast<float4*>(&g_gs[g * Ss + 4 * q]), v);
}

// ---------------------------------------------------------------------------
__global__ void __launch_bounds__(128) readout_kernel(
    const float* __restrict__ Wo1, const float* __restrict__ bo1,
    const float* __restrict__ go, const float* __restrict__ beo,
    const float* __restrict__ Wo2, const float* __restrict__ bo2,
    float* __restrict__ out)
{
    __shared__ float sW[32 * 128];
    __shared__ float sb[128], sg[128], sbe[128];
    __shared__ float sW2[256];
    __shared__ float sb2[2];

    int tid = threadIdx.x;
    for (int i = tid; i < 32 * 128; i += 128) sW[i] = Wo1[i];
    sb[tid] = bo1[tid]; sg[tid] = go[tid]; sbe[tid] = beo[tid];
    sW2[tid] = Wo2[tid];
    sW2[tid + 128] = Wo2[tid + 128];
    if (tid < 2) sb2[tid] = bo2[tid];
    __syncthreads();

    int lane = tid & 31;
    int w = tid >> 5;
    int g = blockIdx.x * 4 + w;
    if (g >= Gg) return;

    float x = g_gs[g * Ss + lane];
    float4 a;
    a.x = sb[4 * lane]; a.y = sb[4 * lane + 1]; a.z = sb[4 * lane + 2]; a.w = sb[4 * lane + 3];
#pragma unroll
    for (int i = 0; i < 32; i++) {
        float xi = __shfl_sync(FULL, x, i);
        float4 wv = *(const float4*)&sW[i * 128 + 4 * lane];
        a.x += xi * wv.x; a.y += xi * wv.y; a.z += xi * wv.z; a.w += xi * wv.w;
    }
    float s = a.x + a.y + a.z + a.w;
    float s2 = a.x * a.x + a.y * a.y + a.z * a.z + a.w * a.w;
#pragma unroll
    for (int o = 16; o; o >>= 1) {
        s += __shfl_xor_sync(FULL, s, o);
        s2 += __shfl_xor_sync(FULL, s2, o);
    }
    float mean = s * (1.f / 128.f);
    float var = s2 * (1.f / 128.f) - mean * mean;
    float rstd = rsqrtf(var + LN_EPS);
    float h0 = lrelu((a.x - mean) * rstd * sg[4 * lane + 0] + sbe[4 * lane + 0]);
    float h1 = lrelu((a.y - mean) * rstd * sg[4 * lane + 1] + sbe[4 * lane + 1]);
    float h2 = lrelu((a.z - mean) * rstd * sg[4 * lane + 2] + sbe[4 * lane + 2]);
    float h3 = lrelu((a.w - mean) * rstd * sg[4 * lane + 3] + sbe[4 * lane + 3]);

    float p0 = h0 * sW2[(4 * lane + 0) * 2] + h1 * sW2[(4 * lane + 1) * 2]
             + h2 * sW2[(4 * lane + 2) * 2] + h3 * sW2[(4 * lane + 3) * 2];
    float p1 = h0 * sW2[(4 * lane + 0) * 2 + 1] + h1 * sW2[(4 * lane + 1) * 2 + 1]
             + h2 * sW2[(4 * lane + 2) * 2 + 1] + h3 * sW2[(4 * lane + 3) * 2 + 1];
#pragma unroll
    for (int o = 16; o; o >>= 1) {
        p0 += __shfl_xor_sync(FULL, p0, o);
        p1 += __shfl_xor_sync(FULL, p1, o);
    }
    if (lane == 0) {
        float mu = p0 + sb2[0];
        float v = p1 + sb2[1];
        float sp = (v > 0.f) ? v + log1pf(expf(-v)) : log1pf(expf(v));
        out[g * 2 + 0] = mu;
        out[g * 2 + 1] = sp;
    }
}

// ---------------------------------------------------------------------------
extern "C" void kernel_launch(void* const* d_in, const int* in_sizes, int n_in,
                              void* d_out, int out_size) {
    const int* nf = (const int*)d_in[0];
    const int* nt = (const int*)d_in[1];
    const float* ec = (const float*)d_in[2];
    const int* ngi = (const int*)d_in[3];
    const float* W1 = (const float*)d_in[6];
    const float* b1 = (const float*)d_in[7];
    const float* g1 = (const float*)d_in[8];
    const float* be1 = (const float*)d_in[9];
    const float* W2 = (const float*)d_in[10];
    const float* b2 = (const float*)d_in[11];
    const float* g2 = (const float*)d_in[12];
    const float* be2 = (const float*)d_in[13];
    const float* Wo1 = (const float*)d_in[14];
    const float* bo1 = (const float*)d_in[15];
    const float* go = (const float*)d_in[16];
    const float* beo = (const float*)d_in[17];
    const float* Wo2 = (const float*)d_in[18];
    const float* bo2 = (const float*)d_in[19];
    float* out = (float*)d_out;

    cudaFuncSetAttribute(edge_kernel, cudaFuncAttributeMaxDynamicSharedMemorySize, EDGE_DSMEM);

    zero_kernel<<<4096, 256>>>();

    int cur = 0;
    for (int r = 0; r < ROUNDS; r++) {
        node_gemm_kernel<<<1024, 192>>>(cur, W1, b1);   // also copies state cur -> cur^1
        edge_kernel<<<EDGE_GRID, 192, EDGE_DSMEM>>>(cur, nf, nt, ec,
                                                    W1, g1, be1, W2, b2, g2, be2);
        cur ^= 1;
    }

    graphsum_kernel<<<(Nn * 8 + 255) / 256, 256>>>(cur, ngi);
    readout_kernel<<<(Gg + 3) / 4, 128>>>(Wo1, bo1, go, beo, Wo2, bo2, out);
}

// round 9
// speedup vs baseline: 1.1204x; 1.1204x over previous
#include <cuda_runtime.h>
#include <cuda_bf16.h>
#include <math.h>
#include <stdint.h>

#define FULL 0xffffffffu
typedef unsigned long long u64;

constexpr int Nn = 100000;
constexpr int Ee = 1600000;
constexpr int Gg = 1000;
constexpr int Ss = 32;
constexpr int Hh = 128;
constexpr int ROUNDS = 5;
constexpr float NEG_SLOPE = 0.01f;
constexpr float LN_EPS = 1e-5f;

constexpr int APITCH = 272;
constexpr int AWARP = 16 * APITCH;
constexpr int EDGE_WARPS = 8;                       // 256-thread blocks (proven config)
constexpr int OFF_B_H = EDGE_WARPS * 2 * AWARP;     // 69632
constexpr int OFF_B_L = OFF_B_H + 32 * APITCH;      // 78336
constexpr int EDGE_DSMEM = OFF_B_L + 32 * APITCH;   // 87040  (2 blocks/SM)
constexpr int EDGE_GRID = 296;

__device__ float g_state[2][Nn * Ss];
__device__ float g_y[Nn * Hh];
__device__ float4 g_stats[Nn];
__device__ float g_gs[Gg * Ss];

__device__ __forceinline__ float lrelu(float v) { return v >= 0.f ? v : NEG_SLOPE * v; }

// ---- packed f32x2 helpers ----
__device__ __forceinline__ u64 pack2(float lo, float hi) {
    u64 r; asm("mov.b64 %0,{%1,%2};" : "=l"(r) : "f"(lo), "f"(hi)); return r;
}
__device__ __forceinline__ void unpack2(u64 v, float& lo, float& hi) {
    asm("mov.b64 {%0,%1},%2;" : "=f"(lo), "=f"(hi) : "l"(v));
}
__device__ __forceinline__ u64 fma2(u64 a, u64 b, u64 c) {
    u64 d; asm("fma.rn.f32x2 %0,%1,%2,%3;" : "=l"(d) : "l"(a), "l"(b), "l"(c)); return d;
}
__device__ __forceinline__ u64 add2(u64 a, u64 b) {
    u64 d; asm("add.rn.f32x2 %0,%1,%2;" : "=l"(d) : "l"(a), "l"(b)); return d;
}
__device__ __forceinline__ u64 mul2(u64 a, u64 b) {
    u64 d; asm("mul.rn.f32x2 %0,%1,%2;" : "=l"(d) : "l"(a), "l"(b)); return d;
}

__device__ __forceinline__ uint32_t smem_u32(const void* p) {
    uint32_t a;
    asm("{ .reg .u64 t; cvta.to.shared.u64 t, %1; cvt.u32.u64 %0, t; }" : "=r"(a) : "l"(p));
    return a;
}

__device__ __forceinline__ void ldsm4(uint32_t r[4], uint32_t addr) {
    asm volatile("ldmatrix.sync.aligned.m8n8.x4.shared.b16 {%0,%1,%2,%3}, [%4];"
                 : "=r"(r[0]), "=r"(r[1]), "=r"(r[2]), "=r"(r[3]) : "r"(addr));
}

__device__ __forceinline__ void mma16816(float acc[4], const uint32_t a[4],
                                         uint32_t b0, uint32_t b1) {
    asm volatile(
        "mma.sync.aligned.m16n8k16.row.col.f32.bf16.bf16.f32 "
        "{%0,%1,%2,%3}, {%4,%5,%6,%7}, {%8,%9}, {%0,%1,%2,%3};"
        : "+f"(acc[0]), "+f"(acc[1]), "+f"(acc[2]), "+f"(acc[3])
        : "r"(a[0]), "r"(a[1]), "r"(a[2]), "r"(a[3]), "r"(b0), "r"(b1));
}

// ---------------------------------------------------------------------------
__global__ void zero_kernel() {
    int i = blockIdx.x * blockDim.x + threadIdx.x;
    int stride = gridDim.x * blockDim.x;
    for (int k = i; k < Nn * Ss; k += stride) g_state[0][k] = 0.f;
    for (int k = i; k < Gg * Ss; k += stride) g_gs[k] = 0.f;
}

// ---------------------------------------------------------------------------
// y = state @ W1[:32] + b1 ; stats (Sy,Qy,P) ; fused copy.  4 nodes/warp.
__global__ void __launch_bounds__(192) node_gemm_kernel(
    int inb, const float* __restrict__ W1, const float* __restrict__ b1)
{
    __shared__ float sW1[32 * 128];
    __shared__ float sb1[128];
    const float* __restrict__ state_in = g_state[inb];
    float* __restrict__ state_out = g_state[inb ^ 1];

    int tid = threadIdx.x;
    for (int i = tid; i < 32 * 128; i += 192) sW1[i] = W1[i];
    if (tid < 128) sb1[tid] = b1[tid];
    __syncthreads();

    int lane = tid & 31;
    int w = tid >> 5;
    int warp_global = blockIdx.x * 6 + w;
    int nwarps = gridDim.x * 6;
    int ngroups = Nn / 4;

    float4 b1v = *(const float4*)&sb1[4 * lane];
    float4 w32v = *(const float4*)&W1[32 * 128 + 4 * lane];

    for (int g = warp_global; g < ngroups; g += nwarps) {
        int nbase = g * 4;
        float x0 = state_in[(nbase + 0) * Ss + lane];
        float x1 = state_in[(nbase + 1) * Ss + lane];
        float x2 = state_in[(nbase + 2) * Ss + lane];
        float x3 = state_in[(nbase + 3) * Ss + lane];

        state_out[(nbase + 0) * Ss + lane] = x0;   // fused copy
        state_out[(nbase + 1) * Ss + lane] = x1;
        state_out[(nbase + 2) * Ss + lane] = x2;
        state_out[(nbase + 3) * Ss + lane] = x3;

        float4 a0 = b1v, a1 = b1v, a2 = b1v, a3 = b1v;
#pragma unroll
        for (int i = 0; i < 32; i++) {
            float4 wv = *(const float4*)&sW1[i * 128 + 4 * lane];
            float s0 = __shfl_sync(FULL, x0, i);
            float s1 = __shfl_sync(FULL, x1, i);
            float s2 = __shfl_sync(FULL, x2, i);
            float s3 = __shfl_sync(FULL, x3, i);
            a0.x += s0 * wv.x; a0.y += s0 * wv.y; a0.z += s0 * wv.z; a0.w += s0 * wv.w;
            a1.x += s1 * wv.x; a1.y += s1 * wv.y; a1.z += s1 * wv.z; a1.w += s1 * wv.w;
            a2.x += s2 * wv.x; a2.y += s2 * wv.y; a2.z += s2 * wv.z; a2.w += s2 * wv.w;
            a3.x += s3 * wv.x; a3.y += s3 * wv.y; a3.z += s3 * wv.z; a3.w += s3 * wv.w;
        }
        *(float4*)&g_y[(nbase + 0) * Hh + 4 * lane] = a0;
        *(float4*)&g_y[(nbase + 1) * Hh + 4 * lane] = a1;
        *(float4*)&g_y[(nbase + 2) * Hh + 4 * lane] = a2;
        *(float4*)&g_y[(nbase + 3) * Hh + 4 * lane] = a3;

#pragma unroll
        for (int e = 0; e < 4; e++) {
            float4 a = (e == 0) ? a0 : (e == 1) ? a1 : (e == 2) ? a2 : a3;
            float s = a.x + a.y + a.z + a.w;
            float q = a.x * a.x + a.y * a.y + a.z * a.z + a.w * a.w;
            float p = a.x * w32v.x + a.y * w32v.y + a.z * w32v.z + a.w * w32v.w;
#pragma unroll
            for (int o = 16; o; o >>= 1) {
                s += __shfl_xor_sync(FULL, s, o);
                q += __shfl_xor_sync(FULL, q, o);
                p += __shfl_xor_sync(FULL, p, o);
            }
            if (lane == 0) g_stats[nbase + e] = make_float4(s, q, p, 0.f);
        }
    }
}

// ---------------------------------------------------------------------------
// Edge kernel: 256 threads, 2 blocks/SM (proven optimum). Permuted B columns,
// packed f32x2 LN2, nt loads hoisted above the MMA loop.
__global__ void __launch_bounds__(256, 2) edge_kernel(
    int inb,
    const int* __restrict__ nf, const int* __restrict__ nt,
    const float* __restrict__ ec,
    const float* __restrict__ W1,
    const float* __restrict__ g1, const float* __restrict__ be1,
    const float* __restrict__ W2, const float* __restrict__ b2,
    const float* __restrict__ g2, const float* __restrict__ be2)
{
    extern __shared__ char dsm[];
    uint32_t sbase = smem_u32(dsm);

    int tid = threadIdx.x;
    int lane = tid & 31;
    int wid = tid >> 5;

    // B staging with column permutation pi(8t+2q+r) = 8q+2t+r
    for (int p = tid; p < 32 * 128; p += 256) {
        int n = p >> 7;
        int k = p & 127;
        int t = n >> 3, q0 = (n >> 1) & 3, r = n & 1;
        int pn = 8 * q0 + 2 * t + r;
        float wv = W2[k * 32 + pn];
        __nv_bfloat16 hb = __float2bfloat16(wv);
        __nv_bfloat16 lb = __float2bfloat16(wv - __bfloat162float(hb));
        *(__nv_bfloat16*)(dsm + OFF_B_H + n * APITCH + k * 2) = hb;
        *(__nv_bfloat16*)(dsm + OFF_B_L + n * APITCH + k * 2) = lb;
    }
    __syncthreads();

    float4 w32v = *(const float4*)&W1[32 * 128 + 4 * lane];
    float4 g1v  = *(const float4*)&g1[4 * lane];
    float4 be1v = *(const float4*)&be1[4 * lane];

    float Sw = w32v.x + w32v.y + w32v.z + w32v.w;
    float Qw = w32v.x * w32v.x + w32v.y * w32v.y + w32v.z * w32v.z + w32v.w * w32v.w;
#pragma unroll
    for (int o = 16; o; o >>= 1) {
        Sw += __shfl_xor_sync(FULL, Sw, o);
        Qw += __shfl_xor_sync(FULL, Qw, o);
    }

    int q = lane & 3;
    int rA = lane >> 2;
    int rB = rA + 8;

    u64 b2p[4], g2p[4], be2p[4];
#pragma unroll
    for (int t = 0; t < 4; t++) {
        int c = 8 * q + 2 * t;
        b2p[t]  = pack2(b2[c],  b2[c + 1]);
        g2p[t]  = pack2(g2[c],  g2[c + 1]);
        be2p[t] = pack2(be2[c], be2[c + 1]);
    }
    const u64 C001 = pack2(NEG_SLOPE, NEG_SLOPE);

    char* aStoreH = dsm + wid * 2 * AWARP + lane * 8;
    char* aStoreL = aStoreH + AWARP;

    int aRow = lane & 15;
    int aColB = ((lane >> 4) & 1) * 16;
    uint32_t ldAH = sbase + wid * 2 * AWARP + aRow * APITCH + aColB;
    uint32_t ldAL = ldAH + AWARP;

    int bRow = ((lane >> 4) & 1) * 8 + (lane & 7);
    int bKB = ((lane >> 3) & 1) * 16;
    uint32_t ldBH01 = sbase + OFF_B_H + bRow * APITCH + bKB;
    uint32_t ldBH23 = ldBH01 + 16 * APITCH;
    uint32_t ldBL01 = sbase + OFF_B_L + bRow * APITCH + bKB;
    uint32_t ldBL23 = ldBL01 + 16 * APITCH;

    const float4* __restrict__ yv = (const float4*)g_y;
    float* __restrict__ state_out = g_state[inb ^ 1];

    int ngroups = Ee / 16;
    int wg = blockIdx.x * EDGE_WARPS + wid;
    int nw = gridDim.x * EDGE_WARPS;

    for (int g = wg; g < ngroups; g += nw) {
        int base = g * 16;

        // ---- gather + stats-based LN1 + bf16 split + stage ----
#pragma unroll
        for (int j = 0; j < 4; j++) {
            int4 NF = *(const int4*)&nf[base + 4 * j];
            float4 C = *(const float4*)&ec[base + 4 * j];
            int srcs[4] = {NF.x, NF.y, NF.z, NF.w};
            float cs[4] = {C.x, C.y, C.z, C.w};
#pragma unroll
            for (int e = 0; e < 4; e++) {
                int src = srcs[e];
                float c = cs[e];
                float4 st = g_stats[src];
                float4 a = yv[src * (Hh / 4) + lane];
                a.x = fmaf(c, w32v.x, a.x);
                a.y = fmaf(c, w32v.y, a.y);
                a.z = fmaf(c, w32v.z, a.z);
                a.w = fmaf(c, w32v.w, a.w);

                float s = fmaf(c, Sw, st.x);
                float qq = fmaf(c * c, Qw, fmaf(2.f * c, st.z, st.y));
                float mean = s * (1.f / 128.f);
                float var = qq * (1.f / 128.f) - mean * mean;
                float rstd = rsqrtf(var + LN_EPS);

                float4 hv;
                hv.x = lrelu(fmaf((a.x - mean) * rstd, g1v.x, be1v.x));
                hv.y = lrelu(fmaf((a.y - mean) * rstd, g1v.y, be1v.y));
                hv.z = lrelu(fmaf((a.z - mean) * rstd, g1v.z, be1v.z));
                hv.w = lrelu(fmaf((a.w - mean) * rstd, g1v.w, be1v.w));

                __nv_bfloat162 h01 = __float22bfloat162_rn(make_float2(hv.x, hv.y));
                __nv_bfloat162 h23 = __float22bfloat162_rn(make_float2(hv.z, hv.w));
                float2 f01 = __bfloat1622float2(h01);
                float2 f23 = __bfloat1622float2(h23);
                __nv_bfloat162 l01 = __float22bfloat162_rn(make_float2(hv.x - f01.x, hv.y - f01.y));
                __nv_bfloat162 l23 = __float22bfloat162_rn(make_float2(hv.z - f23.x, hv.w - f23.y));
                u64 packh = (u64)(*(uint32_t*)&h01) | ((u64)(*(uint32_t*)&h23) << 32);
                u64 packl = (u64)(*(uint32_t*)&l01) | ((u64)(*(uint32_t*)&l23) << 32);
                int row = 4 * j + e;
                *(u64*)(aStoreH + row * APITCH) = packh;
                *(u64*)(aStoreL + row * APITCH) = packl;
            }
        }
        __syncwarp();

        // hoist destination loads: latency hides behind the MMA section
        int dstA = __ldg(&nt[base + rA]);
        int dstB = __ldg(&nt[base + rB]);

        // ---- MMA: D = Ah@Bh + Ah@Bl + Al@Bh ----
        float acc[4][4];
#pragma unroll
        for (int t = 0; t < 4; t++)
#pragma unroll
            for (int j2 = 0; j2 < 4; j2++) acc[t][j2] = 0.f;

#pragma unroll
        for (int k = 0; k < 8; k++) {
            uint32_t ah[4], al[4], bh01[4], bh23[4], bl01[4], bl23[4];
            ldsm4(ah, ldAH + k * 32);
            ldsm4(al, ldAL + k * 32);
            ldsm4(bh01, ldBH01 + k * 32);
            ldsm4(bh23, ldBH23 + k * 32);
            ldsm4(bl01, ldBL01 + k * 32);
            ldsm4(bl23, ldBL23 + k * 32);

            mma16816(acc[0], ah, bh01[0], bh01[1]);
            mma16816(acc[1], ah, bh01[2], bh01[3]);
            mma16816(acc[2], ah, bh23[0], bh23[1]);
            mma16816(acc[3], ah, bh23[2], bh23[3]);

            mma16816(acc[0], ah, bl01[0], bl01[1]);
            mma16816(acc[1], ah, bl01[2], bl01[3]);
            mma16816(acc[2], ah, bl23[0], bl23[1]);
            mma16816(acc[3], ah, bl23[2], bl23[3]);

            mma16816(acc[0], al, bh01[0], bh01[1]);
            mma16816(acc[1], al, bh01[2], bh01[3]);
            mma16816(acc[2], al, bh23[0], bh23[1]);
            mma16816(acc[3], al, bh23[2], bh23[3]);
        }
        __syncwarp();

        // ---- epilogue: packed bias + LN2 (quad reduction) + float4 scatter ----
        u64 mA[4], mB[4];
#pragma unroll
        for (int t = 0; t < 4; t++) {
            mA[t] = add2(pack2(acc[t][0], acc[t][1]), b2p[t]);
            mB[t] = add2(pack2(acc[t][2], acc[t][3]), b2p[t]);
        }
        u64 sA2 = add2(add2(mA[0], mA[1]), add2(mA[2], mA[3]));
        u64 sB2 = add2(add2(mB[0], mB[1]), add2(mB[2], mB[3]));
        u64 qA2 = fma2(mA[0], mA[0], fma2(mA[1], mA[1], fma2(mA[2], mA[2], mul2(mA[3], mA[3]))));
        u64 qB2 = fma2(mB[0], mB[0], fma2(mB[1], mB[1], fma2(mB[2], mB[2], mul2(mB[3], mB[3]))));
        float t0, t1;
        unpack2(sA2, t0, t1); float sA = t0 + t1;
        unpack2(qA2, t0, t1); float qA = t0 + t1;
        unpack2(sB2, t0, t1); float sB = t0 + t1;
        unpack2(qB2, t0, t1); float qB = t0 + t1;
#pragma unroll
        for (int o = 2; o; o >>= 1) {
            sA += __shfl_xor_sync(FULL, sA, o);
            qA += __shfl_xor_sync(FULL, qA, o);
            sB += __shfl_xor_sync(FULL, sB, o);
            qB += __shfl_xor_sync(FULL, qB, o);
        }
        float meanA = sA * (1.f / 32.f);
        float rstdA = rsqrtf(qA * (1.f / 32.f) - meanA * meanA + LN_EPS);
        float meanB = sB * (1.f / 32.f);
        float rstdB = rsqrtf(qB * (1.f / 32.f) - meanB * meanB + LN_EPS);

        u64 rA2p = pack2(rstdA, rstdA), nmA2 = pack2(-meanA, -meanA);
        u64 rB2p = pack2(rstdB, rstdB), nmB2 = pack2(-meanB, -meanB);

        float vA[8], vB[8];
#pragma unroll
        for (int t = 0; t < 4; t++) {
            u64 agA = mul2(rA2p, g2p[t]);
            u64 offA = fma2(nmA2, agA, be2p[t]);
            u64 hA = fma2(mA[t], agA, offA);
            u64 pA = mul2(hA, C001);
            float h0, h1, p0, p1;
            unpack2(hA, h0, h1); unpack2(pA, p0, p1);
            vA[2 * t] = fmaxf(h0, p0); vA[2 * t + 1] = fmaxf(h1, p1);

            u64 agB = mul2(rB2p, g2p[t]);
            u64 offB = fma2(nmB2, agB, be2p[t]);
            u64 hB = fma2(mB[t], agB, offB);
            u64 pB = mul2(hB, C001);
            unpack2(hB, h0, h1); unpack2(pB, p0, p1);
            vB[2 * t] = fmaxf(h0, p0); vB[2 * t + 1] = fmaxf(h1, p1);
        }

        float* rowA = &state_out[dstA * Ss + 8 * q];
        float* rowB = &state_out[dstB * Ss + 8 * q];
        atomicAdd((float4*)&rowA[0], make_float4(vA[0], vA[1], vA[2], vA[3]));
        atomicAdd((float4*)&rowA[4], make_float4(vA[4], vA[5], vA[6], vA[7]));
        atomicAdd((float4*)&rowB[0], make_float4(vB[0], vB[1], vB[2], vB[3]));
        atomicAdd((float4*)&rowB[4], make_float4(vB[4], vB[5], vB[6], vB[7]));
    }
}

// ---------------------------------------------------------------------------
__global__ void graphsum_kernel(int inb, const int* __restrict__ ngi) {
    int t = blockIdx.x * blockDim.x + threadIdx.x;
    int total = Nn * (Ss / 4);
    if (t >= total) return;
    int n = t >> 3;
    int q = t & 7;
    const float4* s = reinterpret_cast<const float4*>(g_state[inb]);
    float4 v = s[t];
    int g = ngi[n];
    atomicAdd(reinterpret_cast<float4*>(&g_gs[g * Ss + 4 * q]), v);
}

// ---------------------------------------------------------------------------
__global__ void __launch_bounds__(128) readout_kernel(
    const float* __restrict__ Wo1, const float* __restrict__ bo1,
    const float* __restrict__ go, const float* __restrict__ beo,
    const float* __restrict__ Wo2, const float* __restrict__ bo2,
    float* __restrict__ out)
{
    __shared__ float sW[32 * 128];
    __shared__ float sb[128], sg[128], sbe[128];
    __shared__ float sW2[256];
    __shared__ float sb2[2];

    int tid = threadIdx.x;
    for (int i = tid; i < 32 * 128; i += 128) sW[i] = Wo1[i];
    sb[tid] = bo1[tid]; sg[tid] = go[tid]; sbe[tid] = beo[tid];
    sW2[tid] = Wo2[tid];
    sW2[tid + 128] = Wo2[tid + 128];
    if (tid < 2) sb2[tid] = bo2[tid];
    __syncthreads();

    int lane = tid & 31;
    int w = tid >> 5;
    int g = blockIdx.x * 4 + w;
    if (g >= Gg) return;

    float x = g_gs[g * Ss + lane];
    float4 a;
    a.x = sb[4 * lane]; a.y = sb[4 * lane + 1]; a.z = sb[4 * lane + 2]; a.w = sb[4 * lane + 3];
#pragma unroll
    for (int i = 0; i < 32; i++) {
        float xi = __shfl_sync(FULL, x, i);
        float4 wv = *(const float4*)&sW[i * 128 + 4 * lane];
        a.x += xi * wv.x; a.y += xi * wv.y; a.z += xi * wv.z; a.w += xi * wv.w;
    }
    float s = a.x + a.y + a.z + a.w;
    float s2 = a.x * a.x + a.y * a.y + a.z * a.z + a.w * a.w;
#pragma unroll
    for (int o = 16; o; o >>= 1) {
        s += __shfl_xor_sync(FULL, s, o);
        s2 += __shfl_xor_sync(FULL, s2, o);
    }
    float mean = s * (1.f / 128.f);
    float var = s2 * (1.f / 128.f) - mean * mean;
    float rstd = rsqrtf(var + LN_EPS);
    float h0 = lrelu((a.x - mean) * rstd * sg[4 * lane + 0] + sbe[4 * lane + 0]);
    float h1 = lrelu((a.y - mean) * rstd * sg[4 * lane + 1] + sbe[4 * lane + 1]);
    float h2 = lrelu((a.z - mean) * rstd * sg[4 * lane + 2] + sbe[4 * lane + 2]);
    float h3 = lrelu((a.w - mean) * rstd * sg[4 * lane + 3] + sbe[4 * lane + 3]);

    float p0 = h0 * sW2[(4 * lane + 0) * 2] + h1 * sW2[(4 * lane + 1) * 2]
             + h2 * sW2[(4 * lane + 2) * 2] + h3 * sW2[(4 * lane + 3) * 2];
    float p1 = h0 * sW2[(4 * lane + 0) * 2 + 1] + h1 * sW2[(4 * lane + 1) * 2 + 1]
             + h2 * sW2[(4 * lane + 2) * 2 + 1] + h3 * sW2[(4 * lane + 3) * 2 + 1];
#pragma unroll
    for (int o = 16; o; o >>= 1) {
        p0 += __shfl_xor_sync(FULL, p0, o);
        p1 += __shfl_xor_sync(FULL, p1, o);
    }
    if (lane == 0) {
        float mu = p0 + sb2[0];
        float v = p1 + sb2[1];
        float sp = (v > 0.f) ? v + log1pf(expf(-v)) : log1pf(expf(v));
        out[g * 2 + 0] = mu;
        out[g * 2 + 1] = sp;
    }
}

// ---------------------------------------------------------------------------
extern "C" void kernel_launch(void* const* d_in, const int* in_sizes, int n_in,
                              void* d_out, int out_size) {
    const int* nf = (const int*)d_in[0];
    const int* nt = (const int*)d_in[1];
    const float* ec = (const float*)d_in[2];
    const int* ngi = (const int*)d_in[3];
    const float* W1 = (const float*)d_in[6];
    const float* b1 = (const float*)d_in[7];
    const float* g1 = (const float*)d_in[8];
    const float* be1 = (const float*)d_in[9];
    const float* W2 = (const float*)d_in[10];
    const float* b2 = (const float*)d_in[11];
    const float* g2 = (const float*)d_in[12];
    const float* be2 = (const float*)d_in[13];
    const float* Wo1 = (const float*)d_in[14];
    const float* bo1 = (const float*)d_in[15];
    const float* go = (const float*)d_in[16];
    const float* beo = (const float*)d_in[17];
    const float* Wo2 = (const float*)d_in[18];
    const float* bo2 = (const float*)d_in[19];
    float* out = (float*)d_out;

    cudaFuncSetAttribute(edge_kernel, cudaFuncAttributeMaxDynamicSharedMemorySize, EDGE_DSMEM);

    zero_kernel<<<4096, 256>>>();

    int cur = 0;
    for (int r = 0; r < ROUNDS; r++) {
        node_gemm_kernel<<<1024, 192>>>(cur, W1, b1);   // also copies state cur -> cur^1
        edge_kernel<<<EDGE_GRID, 256, EDGE_DSMEM>>>(cur, nf, nt, ec,
                                                    W1, g1, be1, W2, b2, g2, be2);
        cur ^= 1;
    }

    graphsum_kernel<<<(Nn * 8 + 255) / 256, 256>>>(cur, ngi);
    readout_kernel<<<(Gg + 3) / 4, 128>>>(Wo1, bo1, go, beo, Wo2, bo2, out);
}